// round 1
// baseline (speedup 1.0000x reference)
#include <cuda_runtime.h>

// Problem constants (fixed by reference_code structure)
#define ZBLK   128      // z-points per CTA
#define KTOT   204      // total filter components
#define NPATH  60
#define NCOL   324      // D*D = 18*18
#define NBAS   64
#define NHID   64

// lf per (l_in,l_out,lf) combo, in reference enumeration order; each combo -> 4 paths (MUL*MUL)
__constant__ int c_Lc[15] = {0,1,2, 1,0,1,2,1,2, 2,1,2,0,1,2};

__global__ __launch_bounds__(256, 1)
void fused_e3nn_kernel(const float* __restrict__ r,
                       const float* __restrict__ W1,
                       const float* __restrict__ b1,
                       const float* __restrict__ W2,
                       const float* __restrict__ b2,
                       const float* __restrict__ cg,
                       float* __restrict__ out,
                       int Z)
{
    extern __shared__ float sm[];
    float* coeff = sm;                 // [KTOT][ZBLK]  (k-major, z contiguous)
    float* buf   = sm + KTOT * ZBLK;   // phase1: weights; phase2: cg tile [KTOT][128]

    const int tid = threadIdx.x;
    const int z0  = blockIdx.x * ZBLK;

    // ---------------- Phase 0: stage MLP weights into shared (aliased buffer) --------------
    float* Ws1  = buf;                   // [64][64] j-major
    float* Ws2t = buf + NBAS * NHID;     // [60][64] p-major (transposed W2)
    float* b1s  = Ws2t + NPATH * NHID;   // [64]
    float* b2s  = b1s + NHID;            // [60]

    for (int i = tid; i < NBAS * NHID; i += 256) Ws1[i] = W1[i];
    for (int i = tid; i < NHID * NPATH; i += 256) {
        int h = i / NPATH;
        int p = i - h * NPATH;
        Ws2t[p * NHID + h] = W2[i];
    }
    if (tid < NHID)  b1s[tid] = b1[tid];
    if (tid < NPATH) b2s[tid] = b2[tid];
    __syncthreads();

    // ---------------- Phase 1: per-z coefficients (warps 0..3, one z per thread) ----------
    if (tid < ZBLK) {
        const int z = z0 + tid;
        if (z < Z) {
            const float x  = r[3 * z + 0];
            const float y  = r[3 * z + 1];
            const float zz = r[3 * z + 2];
            const float rad = sqrtf(x * x + y * y + zz * zz);
            const float inv = 1.0f / (rad + 1e-12f);
            const float nx = x * inv, ny = y * inv, nz = zz * inv;

            // real spherical harmonics l=0..2, reference ordering
            float Y[9];
            {
                const float c0  = 0.28209479177387814f;
                const float c1  = 0.4886025119029199f;
                const float c2a = 1.0925484305920792f;
                const float c2b = 0.31539156525252005f;
                const float c2c = 0.5462742152960396f;
                Y[0] = c0;
                Y[1] = c1 * ny;
                Y[2] = c1 * nz;
                Y[3] = c1 * nx;
                Y[4] = c2a * nx * ny;
                Y[5] = c2a * ny * nz;
                Y[6] = c2b * (3.0f * nz * nz - 1.0f);
                Y[7] = c2a * nx * nz;
                Y[8] = c2c * (nx * nx - ny * ny);
            }

            // hidden = relu(B @ W1 + b1)
            float H[NHID];
            #pragma unroll
            for (int h = 0; h < NHID; ++h) H[h] = b1s[h];

            const float step = 3.5f / 63.0f;   // linspace(0, R_MAX, 64)
            for (int j = 0; j < NBAS; ++j) {
                const float d  = rad - (float)j * step;
                const float bj = __expf(-4.0f * d * d);     // GAMMA = 4
                const float4* w = (const float4*)&Ws1[j * NHID];
                #pragma unroll
                for (int q = 0; q < NHID / 4; ++q) {
                    float4 wv = w[q];
                    H[4 * q + 0] += bj * wv.x;
                    H[4 * q + 1] += bj * wv.y;
                    H[4 * q + 2] += bj * wv.z;
                    H[4 * q + 3] += bj * wv.w;
                }
            }
            #pragma unroll
            for (int h = 0; h < NHID; ++h) H[h] = fmaxf(H[h], 0.0f);

            // R[p] = H @ W2 + b2, then scatter coeff[k] = R[p] * Y[yoff+m]
            int k = 0;
            for (int c = 0; c < 15; ++c) {
                const int l  = c_Lc[c];
                const int nm = 2 * l + 1;
                const int yo = (l == 0) ? 0 : ((l == 1) ? 1 : 4);
                for (int rep = 0; rep < 4; ++rep) {
                    const int p = c * 4 + rep;
                    float acc = b2s[p];
                    const float4* w = (const float4*)&Ws2t[p * NHID];
                    #pragma unroll
                    for (int q = 0; q < NHID / 4; ++q) {
                        float4 wv = w[q];
                        acc += H[4 * q + 0] * wv.x + H[4 * q + 1] * wv.y
                             + H[4 * q + 2] * wv.z + H[4 * q + 3] * wv.w;
                    }
                    for (int m = 0; m < nm; ++m)
                        coeff[(k + m) * ZBLK + tid] = acc * Y[yo + m];
                    k += nm;
                }
            }
        } else {
            for (int k = 0; k < KTOT; ++k) coeff[k * ZBLK + tid] = 0.0f;
        }
    }

    // ---------------- Phase 2: out[z, 0:324] = coeff[z, :] @ cg[:, :] ---------------------
    // 3 column tiles of 128 (324 -> padded 384). Thread tile: 8 z x 8 cols.
    const int ct = tid & 15;    // 16 col-groups
    const int zt = tid >> 4;    // 16 z-groups

    for (int tile = 0; tile < 3; ++tile) {
        __syncthreads();   // previous tile's cg reads done / coeff writes visible (tile 0)

        const int colbase = tile * 128;
        for (int i = tid; i < KTOT * 128; i += 256) {
            const int k   = i >> 7;
            const int col = i & 127;
            const int gc  = colbase + col;
            buf[i] = (gc < NCOL) ? cg[k * NCOL + gc] : 0.0f;
        }
        __syncthreads();

        float acc[8][8];
        #pragma unroll
        for (int i = 0; i < 8; ++i)
            #pragma unroll
            for (int j = 0; j < 8; ++j) acc[i][j] = 0.0f;

        const float* cA = &coeff[zt * 8];
        const float* cB = &buf[ct * 8];

        #pragma unroll 2
        for (int k = 0; k < KTOT; ++k) {
            const float4 a0  = *(const float4*)(cA + k * 128);
            const float4 a1  = *(const float4*)(cA + k * 128 + 4);
            const float4 bb0 = *(const float4*)(cB + k * 128);
            const float4 bb1 = *(const float4*)(cB + k * 128 + 4);
            const float a[8] = {a0.x, a0.y, a0.z, a0.w, a1.x, a1.y, a1.z, a1.w};
            const float b[8] = {bb0.x, bb0.y, bb0.z, bb0.w, bb1.x, bb1.y, bb1.z, bb1.w};
            #pragma unroll
            for (int i = 0; i < 8; ++i)
                #pragma unroll
                for (int j = 0; j < 8; ++j)
                    acc[i][j] += a[i] * b[j];
        }

        #pragma unroll
        for (int i = 0; i < 8; ++i) {
            const int z = z0 + zt * 8 + i;
            if (z >= Z) continue;
            const int cb = colbase + ct * 8;
            float* op = out + (size_t)z * NCOL + cb;
            if (cb + 8 <= NCOL) {
                *(float4*)(op + 0) = make_float4(acc[i][0], acc[i][1], acc[i][2], acc[i][3]);
                *(float4*)(op + 4) = make_float4(acc[i][4], acc[i][5], acc[i][6], acc[i][7]);
            } else {
                #pragma unroll
                for (int j = 0; j < 8; ++j)
                    if (cb + j < NCOL) op[j] = acc[i][j];
            }
        }
    }
}

extern "C" void kernel_launch(void* const* d_in, const int* in_sizes, int n_in,
                              void* d_out, int out_size)
{
    const float* r   = (const float*)d_in[0];
    const float* W1  = (const float*)d_in[1];
    const float* b1  = (const float*)d_in[2];
    const float* W2  = (const float*)d_in[3];
    const float* b2  = (const float*)d_in[4];
    const float* cg  = (const float*)d_in[5];
    // d_in[6] rf_mix / d_in[7] ylm_mix: structure is hardcoded (block-sparse 0/1 selectors)
    float* out = (float*)d_out;

    const int Z = in_sizes[0] / 3;
    const int nblocks = (Z + ZBLK - 1) / ZBLK;
    const size_t smem = (size_t)2 * KTOT * ZBLK * sizeof(float);   // 208,896 B

    cudaFuncSetAttribute(fused_e3nn_kernel,
                         cudaFuncAttributeMaxDynamicSharedMemorySize, (int)smem);
    fused_e3nn_kernel<<<nblocks, 256, smem>>>(r, W1, b1, W2, b2, cg, out, Z);
}

// round 11
// speedup vs baseline: 1.2167x; 1.2167x over previous
#include <cuda_runtime.h>
#include <cuda_bf16.h>
#include <cstdint>

// ---------------------------------------------------------------------------
// Problem constants
#define KREAL  204
#define KPAD   208           // 13 x k16
#define NPATH  60
#define NCOL   324           // 18*18
#define NPADT  384           // 3 chunks of 128
#define NBAS   64
#define NHID   64
#define ZBLK   128

#define ASTRIDE 432          // bytes per row (208*2=416 padded to 432; conflict-free ldmatrix)
#define TILE_BYTES (128 * ASTRIDE)     // 55296

// SMEM byte offsets
#define SA_H 0u
#define SA_L 55296u
#define SB_H 110592u
#define SB_L 165888u
#define SMEM_REQ 221184

// lf per (l_in,l_out,lf) combo, reference order; 4 paths each
__constant__ int c_Lc[15] = {0,1,2, 1,0,1,2,1,2, 2,1,2,0,1,2};

// Prepared B (cg) bf16 hi/lo, layout [n][k] k-contiguous, [NPADT][KPAD]
__device__ __align__(16) __nv_bfloat16 g_Bh[NPADT * KPAD];
__device__ __align__(16) __nv_bfloat16 g_Bl[NPADT * KPAD];

// ---------------------------------------------------------------------------
__device__ __forceinline__ uint32_t smem_u32(const void* p) {
    uint32_t a;
    asm("{ .reg .u64 t; cvta.to.shared.u64 t, %1; cvt.u32.u64 %0, t; }" : "=r"(a) : "l"(p));
    return a;
}

#define LDSM4(r, addr) \
    asm volatile("ldmatrix.sync.aligned.m8n8.x4.shared.b16 {%0,%1,%2,%3}, [%4];" \
        : "=r"((r)[0]), "=r"((r)[1]), "=r"((r)[2]), "=r"((r)[3]) : "r"(addr))

#define MMA(d, a, b0, b1) \
    asm volatile("mma.sync.aligned.m16n8k16.row.col.f32.bf16.bf16.f32 " \
        "{%0,%1,%2,%3},{%4,%5,%6,%7},{%8,%9},{%0,%1,%2,%3};" \
        : "+f"((d)[0]), "+f"((d)[1]), "+f"((d)[2]), "+f"((d)[3]) \
        : "r"((a)[0]), "r"((a)[1]), "r"((a)[2]), "r"((a)[3]), "r"(b0), "r"(b1))

// ---------------------------------------------------------------------------
// Prep: split cg into bf16 hi/lo, [n][k] layout with zero padding
__global__ void prep_B_kernel(const float* __restrict__ cg) {
    int i = blockIdx.x * blockDim.x + threadIdx.x;
    if (i >= NPADT * KPAD) return;
    int n = i / KPAD;
    int k = i - n * KPAD;
    float v = 0.0f;
    if (k < KREAL && n < NCOL) v = cg[k * NCOL + n];
    __nv_bfloat16 hi = __float2bfloat16(v);
    __nv_bfloat16 lo = __float2bfloat16(v - __bfloat162float(hi));
    g_Bh[i] = hi;
    g_Bl[i] = lo;
}

// ---------------------------------------------------------------------------
__global__ __launch_bounds__(512, 1)
void fused_e3nn_mma_kernel(const float* __restrict__ r,
                           const float* __restrict__ W1,
                           const float* __restrict__ b1,
                           const float* __restrict__ W2,
                           const float* __restrict__ b2,
                           float* __restrict__ out,
                           int Z)
{
    extern __shared__ __align__(16) char S[];
    const uint32_t sbase = smem_u32(S);

    const int tid  = threadIdx.x;
    const int wid  = tid >> 5;
    const int lane = tid & 31;
    const int z0   = blockIdx.x * ZBLK;

    // ---- Stage MLP weights into B region (overwritten later by B chunks) ----
    float* Ws1  = (float*)(S + SB_H);        // [64][64]
    float* Ws2t = Ws1 + NBAS * NHID;         // [60][64] transposed
    float* b1s  = Ws2t + NPATH * NHID;
    float* b2s  = b1s + NHID;
    for (int i = tid; i < NBAS * NHID; i += 512) Ws1[i] = W1[i];
    for (int i = tid; i < NHID * NPATH; i += 512) {
        int h = i / NPATH, p = i - h * NPATH;
        Ws2t[p * NHID + h] = W2[i];
    }
    if (tid < NHID)  b1s[tid] = b1[tid];
    if (tid >= 64 && tid < 64 + NPATH) b2s[tid - 64] = b2[tid - 64];
    __syncthreads();

    // ---- Phase 1: threads 0..127, one z each -> bf16 hi/lo A rows ----
    if (tid < ZBLK) {
        char* rowH = S + SA_H + tid * ASTRIDE;
        char* rowL = S + SA_L + tid * ASTRIDE;
        const int z = z0 + tid;
        if (z < Z) {
            const float x  = r[3 * z + 0];
            const float y  = r[3 * z + 1];
            const float zc = r[3 * z + 2];
            const float rad = sqrtf(x * x + y * y + zc * zc);
            const float inv = 1.0f / (rad + 1e-12f);
            const float nx = x * inv, ny = y * inv, nz = zc * inv;

            float Y[9];
            {
                const float c0  = 0.28209479177387814f;
                const float c1  = 0.4886025119029199f;
                const float c2a = 1.0925484305920792f;
                const float c2b = 0.31539156525252005f;
                const float c2c = 0.5462742152960396f;
                Y[0] = c0;
                Y[1] = c1 * ny;  Y[2] = c1 * nz;  Y[3] = c1 * nx;
                Y[4] = c2a * nx * ny;  Y[5] = c2a * ny * nz;
                Y[6] = c2b * (3.0f * nz * nz - 1.0f);
                Y[7] = c2a * nx * nz;  Y[8] = c2c * (nx * nx - ny * ny);
            }

            float H[NHID];
            #pragma unroll
            for (int h = 0; h < NHID; ++h) H[h] = b1s[h];
            const float step = 3.5f / 63.0f;
            for (int j = 0; j < NBAS; ++j) {
                const float d  = rad - (float)j * step;
                const float bj = __expf(-4.0f * d * d);
                const float4* w = (const float4*)&Ws1[j * NHID];
                #pragma unroll
                for (int q = 0; q < NHID / 4; ++q) {
                    float4 wv = w[q];
                    H[4*q+0] += bj * wv.x;  H[4*q+1] += bj * wv.y;
                    H[4*q+2] += bj * wv.z;  H[4*q+3] += bj * wv.w;
                }
            }
            #pragma unroll
            for (int h = 0; h < NHID; ++h) H[h] = fmaxf(H[h], 0.0f);

            // R[p] -> coeff stream k=0..203, written as bf16x2 pairs
            int k = 0;
            float pend = 0.0f;
            for (int c = 0; c < 15; ++c) {
                const int l  = c_Lc[c];
                const int nm = 2 * l + 1;
                const int yo = (l == 0) ? 0 : ((l == 1) ? 1 : 4);
                for (int rep = 0; rep < 4; ++rep) {
                    const int p = c * 4 + rep;
                    float acc = b2s[p];
                    const float4* w = (const float4*)&Ws2t[p * NHID];
                    #pragma unroll
                    for (int q = 0; q < NHID / 4; ++q) {
                        float4 wv = w[q];
                        acc += H[4*q+0]*wv.x + H[4*q+1]*wv.y
                             + H[4*q+2]*wv.z + H[4*q+3]*wv.w;
                    }
                    for (int m = 0; m < nm; ++m) {
                        const float v = acc * Y[yo + m];
                        if (k & 1) {
                            __nv_bfloat16 h0 = __float2bfloat16(pend);
                            __nv_bfloat16 h1 = __float2bfloat16(v);
                            float l0f = pend - __bfloat162float(h0);
                            float l1f = v    - __bfloat162float(h1);
                            __nv_bfloat16 l0 = __float2bfloat16(l0f);
                            __nv_bfloat16 l1 = __float2bfloat16(l1f);
                            uint32_t hp = (uint32_t)*(uint16_t*)&h0 | ((uint32_t)*(uint16_t*)&h1 << 16);
                            uint32_t lp = (uint32_t)*(uint16_t*)&l0 | ((uint32_t)*(uint16_t*)&l1 << 16);
                            *(uint32_t*)(rowH + (k - 1) * 2) = hp;
                            *(uint32_t*)(rowL + (k - 1) * 2) = lp;
                        } else {
                            pend = v;
                        }
                        ++k;
                    }
                }
            }
            // zero pad k = 204..207
            *(uint32_t*)(rowH + 204 * 2) = 0u;  *(uint32_t*)(rowH + 206 * 2) = 0u;
            *(uint32_t*)(rowL + 204 * 2) = 0u;  *(uint32_t*)(rowL + 206 * 2) = 0u;
        } else {
            for (int q = 0; q < KPAD * 2 / 16; ++q) {
                ((uint4*)rowH)[q] = make_uint4(0, 0, 0, 0);
                ((uint4*)rowL)[q] = make_uint4(0, 0, 0, 0);
            }
        }
    }

    // ---- ldmatrix address precompute ----
    const int mg = wid >> 2;          // 0..3  (M groups of 32 rows)
    const int ng = wid & 3;           // 0..3  (N groups of 32 cols within chunk)
    const int mrow  = (lane & 7) | (lane & 8);          // A: row within 16
    const int kaddA = (lane >> 4) * 8;                  // A: +8 k for upper half
    const int nrow  = (lane & 7) | ((lane & 16) >> 1);  // B: row within 16
    const int kaddB = ((lane >> 3) & 1) * 8;

    const uint32_t aH0 = sbase + SA_H + (uint32_t)(mg * 32 + mrow) * ASTRIDE + kaddA * 2;
    const uint32_t aH1 = aH0 + 16 * ASTRIDE;
    const uint32_t aL0 = aH0 + (SA_L - SA_H);
    const uint32_t aL1 = aH1 + (SA_L - SA_H);
    const uint32_t bRel = (uint32_t)(ng * 32 + nrow) * ASTRIDE + kaddB * 2;

    // output thread mapping within a fragment
    const int tm = lane >> 2;         // 0..7
    const int tn = (lane & 3) * 2;    // 0,2,4,6

    // ---- 3 chunks of 128 output cols ----
    #pragma unroll 1
    for (int chunk = 0; chunk < 3; ++chunk) {
        __syncthreads();   // previous chunk's B reads (and phase-1 writes) complete

        // stage B chunk hi+lo: rows n = chunk*128 .. +127  (26 uint4 per row)
        {
            const uint4* srcH = (const uint4*)(g_Bh + chunk * 128 * KPAD);
            const uint4* srcL = (const uint4*)(g_Bl + chunk * 128 * KPAD);
            for (int i = tid; i < 128 * 26; i += 512) {
                const int row = i / 26;
                const int q   = i - row * 26;
                *(uint4*)(S + SB_H + row * ASTRIDE + q * 16) = srcH[row * 26 + q];
                *(uint4*)(S + SB_L + row * ASTRIDE + q * 16) = srcL[row * 26 + q];
            }
        }
        __syncthreads();

        float acc[2][4][4];
        #pragma unroll
        for (int a = 0; a < 2; ++a)
            #pragma unroll
            for (int b = 0; b < 4; ++b)
                #pragma unroll
                for (int c = 0; c < 4; ++c) acc[a][b][c] = 0.0f;

        const uint32_t bH0 = sbase + SB_H + bRel;
        const uint32_t bH1 = bH0 + 16 * ASTRIDE;
        const uint32_t bL0 = sbase + SB_L + bRel;
        const uint32_t bL1 = bL0 + 16 * ASTRIDE;

        // fused mainloop: per k-step load A-hi/A-lo/B-hi/B-lo once,
        // issue Ah*Bh + Al*Bh + Ah*Bl (24 MMAs per k-step)
        #pragma unroll 1
        for (int ks = 0; ks < 13; ++ks) {
            const uint32_t o = (uint32_t)ks * 32;
            uint32_t B0[4], B1[4], C0[4], C1[4], A0[4], A1[4], L0[4], L1[4];
            LDSM4(B0, bH0 + o);  LDSM4(B1, bH1 + o);
            LDSM4(C0, bL0 + o);  LDSM4(C1, bL1 + o);
            LDSM4(A0, aH0 + o);  LDSM4(A1, aH1 + o);
            LDSM4(L0, aL0 + o);  LDSM4(L1, aL1 + o);
            // A-hi x B-hi
            MMA(acc[0][0], A0, B0[0], B0[1]);  MMA(acc[0][1], A0, B0[2], B0[3]);
            MMA(acc[0][2], A0, B1[0], B1[1]);  MMA(acc[0][3], A0, B1[2], B1[3]);
            MMA(acc[1][0], A1, B0[0], B0[1]);  MMA(acc[1][1], A1, B0[2], B0[3]);
            MMA(acc[1][2], A1, B1[0], B1[1]);  MMA(acc[1][3], A1, B1[2], B1[3]);
            // A-lo x B-hi
            MMA(acc[0][0], L0, B0[0], B0[1]);  MMA(acc[0][1], L0, B0[2], B0[3]);
            MMA(acc[0][2], L0, B1[0], B1[1]);  MMA(acc[0][3], L0, B1[2], B1[3]);
            MMA(acc[1][0], L1, B0[0], B0[1]);  MMA(acc[1][1], L1, B0[2], B0[3]);
            MMA(acc[1][2], L1, B1[0], B1[1]);  MMA(acc[1][3], L1, B1[2], B1[3]);
            // A-hi x B-lo
            MMA(acc[0][0], A0, C0[0], C0[1]);  MMA(acc[0][1], A0, C0[2], C0[3]);
            MMA(acc[0][2], A0, C1[0], C1[1]);  MMA(acc[0][3], A0, C1[2], C1[3]);
            MMA(acc[1][0], A1, C0[0], C0[1]);  MMA(acc[1][1], A1, C0[2], C0[3]);
            MMA(acc[1][2], A1, C1[0], C1[1]);  MMA(acc[1][3], A1, C1[2], C1[3]);
        }

        // epilogue: stream this chunk to GMEM
        const int colbase = chunk * 128 + ng * 32 + tn;
        #pragma unroll
        for (int mf = 0; mf < 2; ++mf) {
            const int zr0 = z0 + mg * 32 + mf * 16 + tm;
            #pragma unroll
            for (int nf = 0; nf < 4; ++nf) {
                const int col = colbase + nf * 8;
                if (col >= NCOL) continue;
                if (zr0 < Z)
                    *(float2*)(out + (size_t)zr0 * NCOL + col) =
                        make_float2(acc[mf][nf][0], acc[mf][nf][1]);
                if (zr0 + 8 < Z)
                    *(float2*)(out + (size_t)(zr0 + 8) * NCOL + col) =
                        make_float2(acc[mf][nf][2], acc[mf][nf][3]);
            }
        }
    }
}

// ---------------------------------------------------------------------------
extern "C" void kernel_launch(void* const* d_in, const int* in_sizes, int n_in,
                              void* d_out, int out_size)
{
    const float* r   = (const float*)d_in[0];
    const float* W1  = (const float*)d_in[1];
    const float* b1  = (const float*)d_in[2];
    const float* W2  = (const float*)d_in[3];
    const float* b2  = (const float*)d_in[4];
    const float* cg  = (const float*)d_in[5];
    float* out = (float*)d_out;

    const int Z = in_sizes[0] / 3;

    prep_B_kernel<<<(NPADT * KPAD + 255) / 256, 256>>>(cg);

    cudaFuncSetAttribute(fused_e3nn_mma_kernel,
                         cudaFuncAttributeMaxDynamicSharedMemorySize, SMEM_REQ);
    const int nblocks = (Z + ZBLK - 1) / ZBLK;
    fused_e3nn_mma_kernel<<<nblocks, 512, SMEM_REQ>>>(r, W1, b1, W2, b2, out, Z);
}